// round 17
// baseline (speedup 1.0000x reference)
#include <cuda_runtime.h>
#include <cstdint>

// Problem dims (fixed: T=2048, B=32, D=512)
#define T_DIM 2048
#define B_DIM 32
#define D_DIM 512
#define M_DIM (T_DIM * B_DIM)   // 65536 GEMM rows
#define BD    (B_DIM * D_DIM)   // 16384 scan lanes

// Scratch: Y = x @ W^T + b (fp32, 134 MB)
__device__ float g_Y[(size_t)M_DIM * D_DIM];

// Work-queue state (zeroed by init_kernel each launch)
__device__ int g_tile;      // GEMM tile queue head
__device__ int g_scan;      // scan item queue head
__device__ int g_done[8];   // per-part completed-tile counters

#define BMT 128
#define BNT 128
#define BKT 16
#define NKT (D_DIM / BKT)      // 32
#define NTILES 2048            // 4 bn x 512 bm
#define MPARTS 8
#define TILES_PER_PART (NTILES / MPARTS)   // 256
#define NWORKERS 296           // 2 CTAs/SM x 148 SMs

#define L_CH  256
#define W_UP  64
#define NCH   (T_DIM / L_CH)   // 8
#define UNR   16
#define SCAN_ITEMS (NCH * (BD / 256))   // 8 x 64 = 512

typedef unsigned long long u64t;

__device__ __forceinline__ void ffma2(u64t& d, u64t a, u64t b) {
    asm("fma.rn.f32x2 %0, %1, %2, %0;" : "+l"(d) : "l"(a), "l"(b));
}
__device__ __forceinline__ u64t pack_dup(float x) {
    u64t r;
    asm("mov.b64 %0, {%1, %1};" : "=l"(r) : "f"(x));
    return r;
}
__device__ __forceinline__ void unpack2(u64t p, float& lo, float& hi) {
    asm("mov.b64 {%0, %1}, %2;" : "=f"(lo), "=f"(hi) : "l"(p));
}
__device__ __forceinline__ void lif_step(float& v, float c, bool& s) {
    v = v + (c - v) * 0.5f;
    s = (v >= 1.0f);
    v = s ? 0.0f : v;
}

__global__ void init_kernel() {
    if (threadIdx.x == 0) { g_tile = 0; g_scan = 0; }
    if (threadIdx.x < 8) g_done[threadIdx.x] = 0;
}

// ---------------------------------------------------------------------------
// Persistent fused kernel: drain GEMM tile queue (frozen round-15 core,
// bit-identical numerics), then drain scan queue with per-part dependency
// spin-waits. Deadlock-free: scan phase begins only after all GEMM tiles are
// claimed by resident CTAs.
// ---------------------------------------------------------------------------
__global__ __launch_bounds__(256, 2)
void fused_kernel(const float* __restrict__ X, const float* __restrict__ Wm,
                  const float* __restrict__ bias, float* __restrict__ out) {
    __shared__ __align__(16) float As[2][BKT][BMT];   // 16 KB
    __shared__ __align__(16) float Bs[2][BKT][BNT];   // 16 KB
    __shared__ int sh_item;

    const int tid  = threadIdx.x;
    const int wid  = tid >> 5;
    const int lane = tid & 31;

    // GEMM thread mapping (round-15 frozen)
    const int warp_m = wid >> 1;
    const int warp_n = wid & 1;
    const int lm     = lane >> 3;
    const int ln     = lane & 7;
    const int tm0    = warp_m * 32 + lm * 8;
    const int bn0    = warp_n * 64 + ln * 4;
    const int gr     = tid >> 2;
    const int gk     = (tid & 3) << 2;

    // ======================= phase 1: GEMM tiles =======================
    for (;;) {
        if (tid == 0) sh_item = atomicAdd(&g_tile, 1);
        __syncthreads();
        const int t = sh_item;
        __syncthreads();
        if (t >= NTILES) break;

        const int bn = (t & 3) * BNT;          // n inner -> X L2 reuse
        const int bm = (t >> 2) * BMT;
        const int part = t >> 8;               // 256 tiles per part

        const float* Xg = X  + (size_t)(bm + gr) * D_DIM + gk;
        const float* Wg = Wm + (size_t)(bn + gr) * D_DIM + gk;

        u64t acc[8][4];
#pragma unroll
        for (int i = 0; i < 8; i++)
#pragma unroll
            for (int j = 0; j < 4; j++) acc[i][j] = 0ull;

        // prologue: chunk 0 -> buffer 0
        {
            float4 a0 = *(const float4*)(Xg);
            float4 a1 = *(const float4*)(Xg + (size_t)64 * D_DIM);
            float4 b0 = *(const float4*)(Wg);
            float4 b1 = *(const float4*)(Wg + (size_t)64 * D_DIM);
#pragma unroll
            for (int c = 0; c < 4; c++) {
                As[0][gk + c][gr]      = ((const float*)&a0)[c];
                As[0][gk + c][gr + 64] = ((const float*)&a1)[c];
                Bs[0][gk + c][gr]      = ((const float*)&b0)[c];
                Bs[0][gk + c][gr + 64] = ((const float*)&b1)[c];
            }
        }
        __syncthreads();

        for (int kt = 1; kt <= NKT; kt++) {
            const int buf = (kt - 1) & 1;

            float4 na0, na1, nb0, nb1;
            if (kt < NKT) {
                const int k0 = kt * BKT;
                na0 = *(const float4*)(Xg + k0);
                na1 = *(const float4*)(Xg + k0 + (size_t)64 * D_DIM);
                nb0 = *(const float4*)(Wg + k0);
                nb1 = *(const float4*)(Wg + k0 + (size_t)64 * D_DIM);
            }

#pragma unroll
            for (int k = 0; k < BKT; k++) {
                float4 a0 = *(const float4*)&As[buf][k][tm0];
                float4 a1 = *(const float4*)&As[buf][k][tm0 + 4];
                u64t ad[8];
                ad[0] = pack_dup(a0.x); ad[1] = pack_dup(a0.y);
                ad[2] = pack_dup(a0.z); ad[3] = pack_dup(a0.w);
                ad[4] = pack_dup(a1.x); ad[5] = pack_dup(a1.y);
                ad[6] = pack_dup(a1.z); ad[7] = pack_dup(a1.w);

                u64t bp[4];
#pragma unroll
                for (int q = 0; q < 2; q++) {
                    ulonglong2 b2 = *(const ulonglong2*)&Bs[buf][k][bn0 + q * 32];
                    bp[q * 2 + 0] = b2.x;
                    bp[q * 2 + 1] = b2.y;
                }

#pragma unroll
                for (int i = 0; i < 8; i++)
#pragma unroll
                    for (int j = 0; j < 4; j++)
                        ffma2(acc[i][j], ad[i], bp[j]);
            }

            if (kt < NKT) {
                const int nbuf = kt & 1;
#pragma unroll
                for (int c = 0; c < 4; c++) {
                    As[nbuf][gk + c][gr]      = ((const float*)&na0)[c];
                    As[nbuf][gk + c][gr + 64] = ((const float*)&na1)[c];
                    Bs[nbuf][gk + c][gr]      = ((const float*)&nb0)[c];
                    Bs[nbuf][gk + c][gr + 64] = ((const float*)&nb1)[c];
                }
            }
            __syncthreads();
        }

        // epilogue: + bias, store Y
#pragma unroll
        for (int q = 0; q < 2; q++) {
            const int col = bn + bn0 + q * 32;
            const float4 bi = *(const float4*)(bias + col);
#pragma unroll
            for (int i = 0; i < 8; i++) {
                float v0, v1, v2, v3;
                unpack2(acc[i][q * 2 + 0], v0, v1);
                unpack2(acc[i][q * 2 + 1], v2, v3);
                float4 o = {v0 + bi.x, v1 + bi.y, v2 + bi.z, v3 + bi.w};
                *(float4*)(g_Y + (size_t)(bm + tm0 + i) * D_DIM + col) = o;
            }
        }

        // release: my stores visible, then count this tile done
        __threadfence();
        __syncthreads();
        if (tid == 0) atomicAdd(&g_done[part], 1);
    }

    // ======================= phase 2: scan items =======================
    for (;;) {
        if (tid == 0) sh_item = atomicAdd(&g_scan, 1);
        __syncthreads();
        const int s = sh_item;
        __syncthreads();
        if (s >= SCAN_ITEMS) break;

        const int chunk = s >> 6;          // chunk-major: low deps first
        const int lb    = s & 63;
        const int t0    = chunk * L_CH;
        const int l     = lb * 256 + tid;

        // wait for parts 0..min(chunk+1, 7)
        if (tid == 0) {
            const int np = (chunk + 2 < MPARTS) ? (chunk + 2) : MPARTS;
            for (int p = 0; p < np; p++) {
                while (*(volatile int*)&g_done[p] < TILES_PER_PART)
                    __nanosleep(200);
            }
        }
        __syncthreads();
        __threadfence();   // acquire: g_Y writes for those parts now visible

        unsigned fb[L_CH / 32];
        float v = 0.0f;
        {
            const int tb = (t0 - W_UP < 0) ? 0 : (t0 - W_UP);
            for (int tw = tb; tw < t0; tw += UNR) {
                float c[UNR];
#pragma unroll
                for (int i = 0; i < UNR; i++)
                    c[i] = g_Y[(size_t)(tw + i) * BD + l];
#pragma unroll
                for (int i = 0; i < UNR; i++) { bool sp; lif_step(v, c[i], sp); }
            }
#pragma unroll
            for (int w = 0; w < L_CH / 32; w++) {
                unsigned bits = 0;
#pragma unroll 1
                for (int h = 0; h < 2; h++) {
                    float c[UNR];
#pragma unroll
                    for (int i = 0; i < UNR; i++)
                        c[i] = g_Y[(size_t)(t0 + w * 32 + h * UNR + i) * BD + l];
#pragma unroll
                    for (int i = 0; i < UNR; i++) {
                        bool sp; lif_step(v, c[i], sp);
                        bits |= (unsigned)sp << (h * UNR + i);
                    }
                }
                fb[w] = bits;
            }
        }

        v = 0.0f;
        {
            const int te = (t0 + L_CH + W_UP > T_DIM) ? T_DIM : (t0 + L_CH + W_UP);
            for (int tw = te; tw > t0 + L_CH; tw -= UNR) {
                float c[UNR];
#pragma unroll
                for (int i = 0; i < UNR; i++)
                    c[i] = g_Y[(size_t)(tw - 1 - i) * BD + l];
#pragma unroll
                for (int i = 0; i < UNR; i++) { bool sp; lif_step(v, c[i], sp); }
            }
#pragma unroll
            for (int w = L_CH / 32 - 1; w >= 0; w--) {
                const unsigned bits = fb[w];
#pragma unroll 1
                for (int h = 1; h >= 0; h--) {
                    float c[UNR];
#pragma unroll
                    for (int i = 0; i < UNR; i++)
                        c[i] = g_Y[(size_t)(t0 + w * 32 + h * UNR + (UNR - 1) - i) * BD + l];
#pragma unroll
                    for (int i = 0; i < UNR; i++) {
                        const int ti = h * UNR + (UNR - 1) - i;
                        bool sp; lif_step(v, c[i], sp);
                        out[(size_t)(t0 + w * 32 + ti) * BD + l] =
                            (sp ? 1.0f : 0.0f) + (float)((bits >> ti) & 1u);
                    }
                }
            }
        }
    }
}

// ---------------------------------------------------------------------------
extern "C" void kernel_launch(void* const* d_in, const int* in_sizes, int n_in,
                              void* d_out, int out_size) {
    const float* x = (const float*)d_in[0];
    const float* W = (const float*)d_in[1];
    const float* b = (const float*)d_in[2];
    float* out = (float*)d_out;

    init_kernel<<<1, 32>>>();
    fused_kernel<<<NWORKERS, 256>>>(x, W, b, out);
}